// round 7
// baseline (speedup 1.0000x reference)
#include <cuda_runtime.h>
#include <cuda_bf16.h>
#include <math.h>

#define B   64
#define NT  20000
#define NT1 20001
#define NTP 20128            // padded dec-partial row stride (74*272, 16B aligned)
#define H4  1024
#define HD  256
#define Y_SZ    (B*NT1)
#define ENC_OFF Y_SZ
#define DEC_OFF (Y_SZ + B*HD)

// k4 sparse GEMM config
#define RC   80      // row-chunk blocks in y
#define RPB  250     // rows per block
#define G4   10      // rows per pipelined chunk
#define NCH4 25      // chunks per block

// ---------------- scratch (device globals; no allocations) -----------------
__device__ float g_counts[NT*B];                 // [tag][batch]
__device__ int   g_istat[128];                   // [0:64) sum, [64:128) sumsq
__device__ float g_mu[B], g_rstd[B];
__device__ float g_pacc[RC*B*H4];                // k4 partials (80*64*1024) >= dec 4*64*20128
__device__ float g_psgw[RC*H4], g_psbw[RC*H4];
__device__ float g_h2[B*H4], g_h3[B*H4], g_encb[B*HD], g_dd[B*H4];
__device__ float g_pbuf[32*B*H4];                // small-GEMM split-K partials

__device__ __forceinline__ float gelu_exact(float x){
    return 0.5f * x * (1.0f + erff(x * 0.70710678118654752f));
}
__device__ __forceinline__ void cpa16(void* d, const void* s){
    unsigned a = (unsigned)__cvta_generic_to_shared(d);
    asm volatile("cp.async.ca.shared.global [%0], [%1], 16;" :: "r"(a), "l"(s));
}
__device__ __forceinline__ void cpa4(void* d, const void* s){
    unsigned a = (unsigned)__cvta_generic_to_shared(d);
    asm volatile("cp.async.ca.shared.global [%0], [%1], 4;" :: "r"(a), "l"(s));
}
#define CP_COMMIT() asm volatile("cp.async.commit_group;" ::: "memory")
#define CP_WAIT0()  asm volatile("cp.async.wait_group 0;" ::: "memory")
#define FMA2(a,x,y) asm("fma.rn.f32x2 %0, %1, %2, %0;" : "+l"(a) : "l"(x), "l"(y))
#define PACK2(o,f)  asm("mov.b64 %0, {%1,%1};" : "=l"(o) : "f"(f))
#define UNPK(l,h,a) asm("mov.b64 {%0,%1}, %2;" : "=f"(l), "=f"(h) : "l"(a))

// ---------------- K1: scatter multi-hot counts (also zeros istat) -----------
__global__ void k1_scatter(const int* __restrict__ tags){
    int p = blockIdx.x*256 + threadIdx.x;       // (b,f) pair, 8192 total
    if (blockIdx.x == 0 && threadIdx.x < 128) g_istat[threadIdx.x] = 0;
    if (p >= B*128) return;
    int b = p >> 7;
    const int* t = tags + p*16;
    int v[16];
    #pragma unroll
    for (int i = 0; i < 16; i++) v[i] = t[i];
    #pragma unroll
    for (int i = 0; i < 16; i++){
        bool dup = false;
        #pragma unroll
        for (int s = 0; s < 16; s++) if (s < i) dup = dup || (v[s] == v[i]);
        if (!dup) atomicAdd(&g_counts[v[i]*B + b], 1.0f);
    }
}

// ---------------- K2: per-batch stats (integer-exact, deterministic) --------
__global__ void k2a_stats(){
    int tid = threadIdx.x;
    int b = tid & 63;
    int s = 0, sq = 0;
    for (int idx = blockIdx.x*256 + tid; idx < NT*B; idx += 160*256){
        int c = __float2int_rn(g_counts[idx]);
        s += c; sq += c*c;
    }
    atomicAdd(&g_istat[b], s);
    atomicAdd(&g_istat[64 + b], sq);
}

// ---------------- K3: write y (output #1); computes mu/rstd inline ----------
__global__ void __launch_bounds__(256) k3_y(const float* __restrict__ fc,
                                            const float* __restrict__ lng,
                                            const float* __restrict__ lnb,
                                            float* __restrict__ y){
    __shared__ float t[64*65];
    __shared__ float mu_s[64], rs_s[64];
    int tid = threadIdx.x;
    int j0 = blockIdx.x * 64;
    if (tid < 64){
        float mu  = (float)g_istat[tid] / (float)NT;
        float var = (float)g_istat[64 + tid] / (float)NT - mu*mu;
        float rs  = rsqrtf(var + 1e-5f);
        mu_s[tid] = mu; rs_s[tid] = rs;
        if (blockIdx.x == 0){ g_mu[tid] = mu; g_rstd[tid] = rs; }
    }
    #pragma unroll
    for (int i = 0; i < 16; i++){
        int idx = i*256 + tid; int r = idx >> 6, b = idx & 63; int j = j0 + r;
        t[r*65 + b] = (j < NT) ? g_counts[j*B + b] : 0.0f;
    }
    __syncthreads();
    #pragma unroll
    for (int i = 0; i < 16; i++){
        int idx = i*256 + tid; int b = idx >> 6, r = idx & 63; int j = j0 + r;
        if (j < NT)
            y[(size_t)b*NT1 + 1 + j] = (t[r*65 + b] - mu_s[b]) * rs_s[b] * lng[j] + lnb[j];
    }
    if (blockIdx.x == 0 && tid < B) y[(size_t)tid*NT1] = fc[tid] * 0.01f;
}

// ---------------- K4: sparse GEMM1 + column-sums (f32x2, balanced colsum) ---
__device__ __forceinline__ void k4_stage(float* wbuf, float* cbuf, float* gbbuf,
                                         int jb, int cbase, int tid,
                                         const float* __restrict__ w1,
                                         const float* __restrict__ lng,
                                         const float* __restrict__ lnb){
    #pragma unroll
    for (int i = 0; i < 3; i++){
        int idx = i*256 + tid;
        if (idx < G4*64){
            int r = idx >> 6, g = idx & 63;
            cpa16(wbuf + r*256 + g*4, w1 + (size_t)(1 + jb + r)*1024 + cbase + g*4);
        }
    }
    if (tid < G4*16){
        int r = tid >> 4, g = tid & 15;
        cpa16(cbuf + r*64 + g*4, g_counts + (jb + r)*64 + g*4);
    }
    if (tid < G4)          cpa4(gbbuf + tid, lng + jb + tid);
    else if (tid < 2*G4)   cpa4(gbbuf + tid, lnb + jb + tid - G4);
    CP_COMMIT();
}

__global__ void __launch_bounds__(256,2) k4_sparse(const float* __restrict__ w1,
                                                   const float* __restrict__ lng,
                                                   const float* __restrict__ lnb){
    __shared__ __align__(16) float w_t[2][G4*256];    // 20 KB
    __shared__ __align__(16) float cnt_t[2][G4*64];   // 5 KB
    __shared__ float gb[2][2*G4];
    int tid = threadIdx.x, lane = tid & 31, wid = tid >> 5;
    int cbase = blockIdx.x * 256;
    int jbase = blockIdx.y * RPB;

    unsigned long long acc[8][4];
    unsigned long long sgw2[4], sbw2[4];
    #pragma unroll
    for (int i = 0; i < 8; i++)
        #pragma unroll
        for (int j = 0; j < 4; j++) acc[i][j] = 0ull;
    #pragma unroll
    for (int j = 0; j < 4; j++){ sgw2[j] = 0ull; sbw2[j] = 0ull; }

    k4_stage(w_t[0], cnt_t[0], gb[0], jbase, cbase, tid, w1, lng, lnb);

    for (int ch = 0; ch < NCH4; ch++){
        int cur = ch & 1;
        CP_WAIT0();
        __syncthreads();
        if (ch + 1 < NCH4)
            k4_stage(w_t[cur^1], cnt_t[cur^1], gb[cur^1],
                     jbase + (ch + 1)*G4, cbase, tid, w1, lng, lnb);

        const float* wbuf = w_t[cur];
        const float* cbuf = cnt_t[cur];
        #pragma unroll
        for (int r = 0; r < G4; r++){
            const float* wrow = wbuf + r*256;
            ulonglong2 wa = *(const ulonglong2*)(wrow + 4*lane);
            ulonglong2 wb = *(const ulonglong2*)(wrow + 4*lane + 128);
            float gj = gb[cur][r];
            if (((ch*G4 + r) & 7) == wid){          // balanced colsum
                float bj = gb[cur][G4 + r];
                unsigned long long gj2, bj2;
                PACK2(gj2, gj); PACK2(bj2, bj);
                FMA2(sgw2[0], gj2, wa.x); FMA2(sgw2[1], gj2, wa.y);
                FMA2(sgw2[2], gj2, wb.x); FMA2(sgw2[3], gj2, wb.y);
                FMA2(sbw2[0], bj2, wa.x); FMA2(sbw2[1], bj2, wa.y);
                FMA2(sbw2[2], bj2, wb.x); FMA2(sbw2[3], bj2, wb.y);
            }
            float cv[8]; float s = 0.0f;
            #pragma unroll
            for (int i = 0; i < 8; i++){ cv[i] = cbuf[r*64 + wid*8 + i]; s += cv[i]; }
            if (s != 0.0f){                          // warp-uniform
                #pragma unroll
                for (int i = 0; i < 8; i++){
                    if (cv[i] != 0.0f){              // warp-uniform
                        float v = cv[i] * gj;
                        unsigned long long v2; PACK2(v2, v);
                        FMA2(acc[i][0], v2, wa.x); FMA2(acc[i][1], v2, wa.y);
                        FMA2(acc[i][2], v2, wb.x); FMA2(acc[i][3], v2, wb.y);
                    }
                }
            }
        }
    }

    // write partials (cols: 4*lane + {0..3} and +128)
    #pragma unroll
    for (int i = 0; i < 8; i++){
        float* rowp = g_pacc + (size_t)(blockIdx.y*64 + wid*8 + i)*1024 + cbase;
        float l0,h0,l1,h1;
        UNPK(l0,h0,acc[i][0]); UNPK(l1,h1,acc[i][1]);
        *(float4*)(rowp + 4*lane) = make_float4(l0,h0,l1,h1);
        UNPK(l0,h0,acc[i][2]); UNPK(l1,h1,acc[i][3]);
        *(float4*)(rowp + 4*lane + 128) = make_float4(l0,h0,l1,h1);
    }

    // reduce colsums across warps via smem (reuse w_t: 5120 floats >= 4096)
    float* red = &w_t[0][0];
    __syncthreads();
    {
        float l0,h0,l1,h1;
        UNPK(l0,h0,sgw2[0]); UNPK(l1,h1,sgw2[1]);
        *(float4*)(red + wid*256 + 4*lane) = make_float4(l0,h0,l1,h1);
        UNPK(l0,h0,sgw2[2]); UNPK(l1,h1,sgw2[3]);
        *(float4*)(red + wid*256 + 4*lane + 128) = make_float4(l0,h0,l1,h1);
        UNPK(l0,h0,sbw2[0]); UNPK(l1,h1,sbw2[1]);
        *(float4*)(red + 2048 + wid*256 + 4*lane) = make_float4(l0,h0,l1,h1);
        UNPK(l0,h0,sbw2[2]); UNPK(l1,h1,sbw2[3]);
        *(float4*)(red + 2048 + wid*256 + 4*lane + 128) = make_float4(l0,h0,l1,h1);
    }
    __syncthreads();
    {
        float sg = 0.0f, sb = 0.0f;
        #pragma unroll
        for (int w = 0; w < 8; w++){
            sg += red[w*256 + tid];
            sb += red[2048 + w*256 + tid];
        }
        g_psgw[blockIdx.y*1024 + cbase + tid] = sg;
        g_psbw[blockIdx.y*1024 + cbase + tid] = sb;
    }
}

// ---------------- K5 fused: colsum + finalize + gelu + LayerNorm -> h2 ------
__global__ void __launch_bounds__(256) k5_fused(const float* __restrict__ w1,
                                                const float* __restrict__ b1,
                                                const float* __restrict__ fc,
                                                const float* __restrict__ g2,
                                                const float* __restrict__ b2){
    __shared__ float r1[256], r2[256];
    int b = blockIdx.x, tid = threadIdx.x;
    float mu_b = g_mu[b], rs_b = g_rstd[b];
    float fcv = fc[b] * 0.01f;
    float h[4]; float s_sum = 0.0f, s_sq = 0.0f;
    #pragma unroll
    for (int i = 0; i < 4; i++){
        int k = i*256 + tid;
        float s = 0.0f, sg = 0.0f, sb = 0.0f;
        #pragma unroll 8
        for (int rc = 0; rc < RC; rc++){
            s  += g_pacc[(size_t)rc*(B*H4) + b*1024 + k];
            sg += g_psgw[rc*1024 + k];
            sb += g_psbw[rc*1024 + k];
        }
        float logit = fcv * w1[k] + sb - mu_b*rs_b*sg + rs_b*s + b1[k];
        h[i] = gelu_exact(logit);
        s_sum += h[i]; s_sq += h[i]*h[i];
    }
    r1[tid] = s_sum; r2[tid] = s_sq; __syncthreads();
    for (int o = 128; o > 0; o >>= 1){
        if (tid < o){ r1[tid] += r1[tid+o]; r2[tid] += r2[tid+o]; }
        __syncthreads();
    }
    float mu = r1[0] * (1.0f/1024.0f);
    float var = r2[0] * (1.0f/1024.0f) - mu*mu;
    float rs = rsqrtf(var + 1e-5f);
    #pragma unroll
    for (int i = 0; i < 4; i++){
        int k = i*256 + tid;
        g_h2[b*1024 + k] = (h[i] - mu)*rs*g2[k] + b2[k];
    }
}

// ---------------- small GEMM: split-K partial + reduce ----------------------
template<int K, int N, int KPER>
__global__ void __launch_bounds__(256) sg_part(const float* __restrict__ A,
                                               const float* __restrict__ W,
                                               float* __restrict__ P){
    __shared__ float a_s[64*32];
    __shared__ float w_s[32*64];
    int tid = threadIdx.x, lane = tid & 31, wid = tid >> 5;
    int cbase = blockIdx.x*64, kbase = blockIdx.y*KPER;
    float acc[8][2] = {};
    for (int kc = kbase; kc < kbase + KPER; kc += 32){
        #pragma unroll
        for (int i = 0; i < 8; i++){
            int idx = i*256 + tid; int b = idx >> 5, kk = idx & 31;
            a_s[b*32 + kk] = A[b*K + kc + kk];
        }
        #pragma unroll
        for (int i = 0; i < 8; i++){
            int idx = i*256 + tid; int kk = idx >> 6, c = idx & 63;
            w_s[kk*64 + c] = W[(size_t)(kc + kk)*N + cbase + c];
        }
        __syncthreads();
        #pragma unroll
        for (int kk = 0; kk < 32; kk++){
            float av[8], wv0, wv1;
            #pragma unroll
            for (int i = 0; i < 8; i++) av[i] = a_s[(wid*8 + i)*32 + kk];
            wv0 = w_s[kk*64 + lane]; wv1 = w_s[kk*64 + lane + 32];
            #pragma unroll
            for (int i = 0; i < 8; i++){
                acc[i][0] += av[i]*wv0;
                acc[i][1] += av[i]*wv1;
            }
        }
        __syncthreads();
    }
    #pragma unroll
    for (int i = 0; i < 8; i++){
        P[blockIdx.y*(64*N) + (wid*8 + i)*N + cbase + lane]      = acc[i][0];
        P[blockIdx.y*(64*N) + (wid*8 + i)*N + cbase + lane + 32] = acc[i][1];
    }
}

template<int S, int N, bool ACT>
__global__ void sg_reduce(const float* __restrict__ P, const float* __restrict__ bias,
                          float* __restrict__ out, float* __restrict__ out2){
    int i = blockIdx.x*256 + threadIdx.x;
    if (i >= 64*N) return;
    float s = bias[i % N];
    #pragma unroll
    for (int p = 0; p < S; p++) s += P[p*64*N + i];
    if (ACT) s = gelu_exact(s);
    out[i] = s;
    if (out2) out2[i] = s;
}

// ---------------- K10: decoder GEMM [64x1024]@[1024x20001] ------------------
#define KC10 16
__global__ void __launch_bounds__(256,2) k10_part(const float* __restrict__ wd2,
                                                  float* __restrict__ P){
    extern __shared__ __align__(16) float dsm[];
    float* w_s  = dsm;          // [2][16*272]
    float* d_sm = dsm + 8704;   // [2][16*130]
    int tid = threadIdx.x, lane = tid & 31, wid = tid >> 5;
    int cbase = blockIdx.x * 272;
    int kbase = blockIdx.y * 256;

    unsigned long long acc[8][4];
    float accx[8];
    #pragma unroll
    for (int i = 0; i < 8; i++){
        accx[i] = 0.0f;
        #pragma unroll
        for (int j = 0; j < 4; j++) acc[i][j] = 0ull;
    }
    float dreg[4];

    {
        #pragma unroll
        for (int i = 0; i < 17; i++){
            int idx = i*256 + tid; int r = idx / 272, c = idx - r*272;
            int gc = cbase + c;
            float* dst = w_s + r*272 + c;
            if (gc < NT1) cpa4(dst, wd2 + (size_t)(kbase + r)*NT1 + gc);
            else *dst = 0.0f;
        }
        CP_COMMIT();
        #pragma unroll
        for (int i = 0; i < 4; i++){
            int idx = i*256 + tid; int b = idx >> 4, k = idx & 15;
            dreg[i] = g_dd[b*1024 + kbase + k];
        }
        #pragma unroll
        for (int i = 0; i < 4; i++){
            int idx = i*256 + tid; int b = idx >> 4, k = idx & 15;
            d_sm[k*130 + 2*b] = dreg[i]; d_sm[k*130 + 2*b + 1] = dreg[i];
        }
    }

    for (int ch = 0; ch < 16; ch++){
        int cur = ch & 1;
        CP_WAIT0();
        __syncthreads();
        if (ch + 1 < 16){
            int kpos = kbase + (ch + 1)*KC10;
            float* wdst = w_s + (cur^1)*4352;
            #pragma unroll
            for (int i = 0; i < 17; i++){
                int idx = i*256 + tid; int r = idx / 272, c = idx - r*272;
                int gc = cbase + c;
                float* dst = wdst + r*272 + c;
                if (gc < NT1) cpa4(dst, wd2 + (size_t)(kpos + r)*NT1 + gc);
                else *dst = 0.0f;
            }
            CP_COMMIT();
            #pragma unroll
            for (int i = 0; i < 4; i++){
                int idx = i*256 + tid; int b = idx >> 4, k = idx & 15;
                dreg[i] = g_dd[b*1024 + kpos + k];
            }
        }
        const float* wb = w_s + cur*4352;
        const float* db = d_sm + cur*2080;
        #pragma unroll 4
        for (int k = 0; k < KC10; k++){
            const float* wrow = wb + k*272;
            ulonglong2 wg0 = *(const ulonglong2*)(wrow + 4*lane);
            ulonglong2 wg1 = *(const ulonglong2*)(wrow + 128 + 4*lane);
            float wex = wrow[256 + (lane & 15)];
            const float* drow = db + k*130;
            #pragma unroll
            for (int i = 0; i < 8; i++){
                int b = wid*8 + i;
                unsigned long long dv = *(const unsigned long long*)(drow + 2*b);
                FMA2(acc[i][0], dv, wg0.x); FMA2(acc[i][1], dv, wg0.y);
                FMA2(acc[i][2], dv, wg1.x); FMA2(acc[i][3], dv, wg1.y);
                float dsc = __uint_as_float((unsigned)dv);
                accx[i] = fmaf(dsc, wex, accx[i]);
            }
        }
        if (ch + 1 < 16){
            float* ddst = d_sm + (cur^1)*2080;
            #pragma unroll
            for (int i = 0; i < 4; i++){
                int idx = i*256 + tid; int b = idx >> 4, k = idx & 15;
                ddst[k*130 + 2*b] = dreg[i]; ddst[k*130 + 2*b + 1] = dreg[i];
            }
        }
    }

    size_t obase = (size_t)blockIdx.y * (B*NTP);
    #pragma unroll
    for (int i = 0; i < 8; i++){
        float* rowp = P + obase + (size_t)(wid*8 + i)*NTP + cbase;
        float l0, h0, l1, h1;
        UNPK(l0,h0,acc[i][0]); UNPK(l1,h1,acc[i][1]);
        *(float4*)(rowp + 4*lane) = make_float4(l0, h0, l1, h1);
        UNPK(l0,h0,acc[i][2]); UNPK(l1,h1,acc[i][3]);
        *(float4*)(rowp + 128 + 4*lane) = make_float4(l0, h0, l1, h1);
        if (lane < 16) rowp[256 + lane] = accx[i];
    }
}

__global__ void k10_reduce(const float* __restrict__ P, const float* __restrict__ bd2,
                           float* __restrict__ dec){
    int i = blockIdx.x*256 + threadIdx.x;
    if (i >= B*NT1) return;
    int b = i / NT1;
    int c = i - b*NT1;
    float s = bd2[c];
    #pragma unroll
    for (int p = 0; p < 4; p++) s += P[(size_t)p*(B*NTP) + (size_t)b*NTP + c];
    dec[i] = s;
}

// ---------------- launch -----------------------------------------------------
extern "C" void kernel_launch(void* const* d_in, const int* in_sizes, int n_in,
                              void* d_out, int out_size){
    const int*   tags = (const int*)  d_in[0];
    const float* fc   = (const float*)d_in[1];
    const float* lng  = (const float*)d_in[2];
    const float* lnb  = (const float*)d_in[3];
    const float* w1   = (const float*)d_in[4];
    const float* b1   = (const float*)d_in[5];
    const float* ln2g = (const float*)d_in[6];
    const float* ln2b = (const float*)d_in[7];
    const float* we1  = (const float*)d_in[8];
    const float* be1  = (const float*)d_in[9];
    const float* we2  = (const float*)d_in[10];
    const float* be2  = (const float*)d_in[11];
    const float* wd1  = (const float*)d_in[12];
    const float* bd1  = (const float*)d_in[13];
    const float* wd2  = (const float*)d_in[14];
    const float* bd2  = (const float*)d_in[15];
    float* out = (float*)d_out;

    float *p_counts, *p_h2, *p_h3, *p_enc, *p_dd, *p_pbuf, *p_pacc;
    cudaGetSymbolAddress((void**)&p_counts, g_counts);
    cudaGetSymbolAddress((void**)&p_h2,     g_h2);
    cudaGetSymbolAddress((void**)&p_h3,     g_h3);
    cudaGetSymbolAddress((void**)&p_enc,    g_encb);
    cudaGetSymbolAddress((void**)&p_dd,     g_dd);
    cudaGetSymbolAddress((void**)&p_pbuf,   g_pbuf);
    cudaGetSymbolAddress((void**)&p_pacc,   g_pacc);

    static int smem_set = 0;
    if (!smem_set){
        cudaFuncSetAttribute(k10_part, cudaFuncAttributeMaxDynamicSharedMemorySize, 51456);
        smem_set = 1;
    }

    cudaMemsetAsync(p_counts, 0, (size_t)NT*B*sizeof(float));
    k1_scatter<<<32, 256>>>(tags);
    k2a_stats<<<160, 256>>>();
    k3_y<<<313, 256>>>(fc, lng, lnb, out);
    k4_sparse<<<dim3(4, RC), 256>>>(w1, lng, lnb);
    k5_fused<<<64, 256>>>(w1, b1, fc, ln2g, ln2b);

    // h2 @ we1 (1024->1024) + gelu
    sg_part<1024, 1024, 32><<<dim3(16, 32), 256>>>(p_h2, we1, p_pbuf);
    sg_reduce<32, 1024, true><<<256, 256>>>(p_pbuf, be1, p_h3, (float*)0);
    // h3 @ we2 (1024->256) -> enc (output #2)
    sg_part<1024, 256, 32><<<dim3(4, 32), 256>>>(p_h3, we2, p_pbuf);
    sg_reduce<32, 256, false><<<64, 256>>>(p_pbuf, be2, out + ENC_OFF, p_enc);
    // enc @ wd1 (256->1024) + gelu
    sg_part<256, 1024, 32><<<dim3(16, 8), 256>>>(p_enc, wd1, p_pbuf);
    sg_reduce<8, 1024, true><<<256, 256>>>(p_pbuf, bd1, p_dd, (float*)0);

    // dd @ wd2 (1024->20001) -> dec (output #3)
    k10_part<<<dim3(74, 4), 256, 51456>>>(wd2, p_pacc);
    k10_reduce<<<5001, 256>>>(p_pacc, bd2, out + DEC_OFF);
}

// round 8
// speedup vs baseline: 1.8937x; 1.8937x over previous
#include <cuda_runtime.h>
#include <cuda_bf16.h>
#include <math.h>

#define B   64
#define NT  20000
#define NT1 20001
#define NTP 20128            // padded dec-partial row stride (74*272, 16B aligned)
#define H4  1024
#define HD  256
#define Y_SZ    (B*NT1)
#define ENC_OFF Y_SZ
#define DEC_OFF (Y_SZ + B*HD)

// k4 sparse GEMM config: grid (8 col-blocks x 50 row-blocks), 400 rows/block
#define RC   50
#define RPB  400
#define G4   16
#define NCH4 25

// ---------------- scratch (device globals; no allocations) -----------------
__device__ float g_counts[NT*B];                 // [tag][batch]
__device__ int   g_istat[128];                   // [0:64) sum, [64:128) sumsq
__device__ float g_mu[B], g_rstd[B];
__device__ float g_accum[B*H4];                  // k4 atomic accumulator (L2-resident)
__device__ float g_asgw[H4], g_asbw[H4];         // column-sum accumulators
__device__ float g_pacc[4*B*NTP];                // decoder split-K partials
__device__ float g_h2[B*H4], g_h3[B*H4], g_encb[B*HD], g_dd[B*H4];
__device__ float g_pbuf[32*B*H4];                // small-GEMM split-K partials

__device__ __forceinline__ float gelu_exact(float x){
    return 0.5f * x * (1.0f + erff(x * 0.70710678118654752f));
}
__device__ __forceinline__ void cpa16(void* d, const void* s){
    unsigned a = (unsigned)__cvta_generic_to_shared(d);
    asm volatile("cp.async.ca.shared.global [%0], [%1], 16;" :: "r"(a), "l"(s));
}
__device__ __forceinline__ void cpa4(void* d, const void* s){
    unsigned a = (unsigned)__cvta_generic_to_shared(d);
    asm volatile("cp.async.ca.shared.global [%0], [%1], 4;" :: "r"(a), "l"(s));
}
#define CP_COMMIT() asm volatile("cp.async.commit_group;" ::: "memory")
#define CP_WAIT0()  asm volatile("cp.async.wait_group 0;" ::: "memory")
#define FMA2(a,x,y) asm("fma.rn.f32x2 %0, %1, %2, %0;" : "+l"(a) : "l"(x), "l"(y))
#define UNPK(l,h,a) asm("mov.b64 {%0,%1}, %2;" : "=f"(l), "=f"(h) : "l"(a))

// ---------------- K1: scatter multi-hot counts + zero accumulators ----------
__global__ void k1_scatter(const int* __restrict__ tags){
    int p = blockIdx.x*256 + threadIdx.x;       // (b,f) pair, 8192 total
    if (blockIdx.x == 0 && threadIdx.x < 128) g_istat[threadIdx.x] = 0;
    // zero k4 accumulators (atomic targets) every launch
    for (int z = p; z < B*H4; z += 8192) g_accum[z] = 0.0f;
    if (p < H4){ g_asgw[p] = 0.0f; g_asbw[p] = 0.0f; }
    int b = p >> 7;
    const int* t = tags + p*16;
    int v[16];
    #pragma unroll
    for (int i = 0; i < 16; i++) v[i] = t[i];
    #pragma unroll
    for (int i = 0; i < 16; i++){
        bool dup = false;
        #pragma unroll
        for (int s = 0; s < 16; s++) if (s < i) dup = dup || (v[s] == v[i]);
        if (!dup) atomicAdd(&g_counts[v[i]*B + b], 1.0f);
    }
}

// ---------------- K2: per-batch stats (integer-exact, deterministic) --------
__global__ void k2a_stats(){
    int tid = threadIdx.x;
    int b = tid & 63;
    int s = 0, sq = 0;
    for (int idx = blockIdx.x*256 + tid; idx < NT*B; idx += 160*256){
        int c = __float2int_rn(g_counts[idx]);
        s += c; sq += c*c;
    }
    atomicAdd(&g_istat[b], s);
    atomicAdd(&g_istat[64 + b], sq);
}

// ---------------- K3: write y (output #1); computes mu/rstd inline ----------
__global__ void __launch_bounds__(256) k3_y(const float* __restrict__ fc,
                                            const float* __restrict__ lng,
                                            const float* __restrict__ lnb,
                                            float* __restrict__ y){
    __shared__ float t[64*65];
    __shared__ float mu_s[64], rs_s[64];
    int tid = threadIdx.x;
    int j0 = blockIdx.x * 64;
    if (tid < 64){
        float mu  = (float)g_istat[tid] / (float)NT;
        float var = (float)g_istat[64 + tid] / (float)NT - mu*mu;
        float rs  = rsqrtf(var + 1e-5f);
        mu_s[tid] = mu; rs_s[tid] = rs;
        if (blockIdx.x == 0){ g_mu[tid] = mu; g_rstd[tid] = rs; }
    }
    #pragma unroll
    for (int i = 0; i < 16; i++){
        int idx = i*256 + tid; int r = idx >> 6, b = idx & 63; int j = j0 + r;
        t[r*65 + b] = (j < NT) ? g_counts[j*B + b] : 0.0f;
    }
    __syncthreads();
    #pragma unroll
    for (int i = 0; i < 16; i++){
        int idx = i*256 + tid; int b = idx >> 6, r = idx & 63; int j = j0 + r;
        if (j < NT)
            y[(size_t)b*NT1 + 1 + j] = (t[r*65 + b] - mu_s[b]) * rs_s[b] * lng[j] + lnb[j];
    }
    if (blockIdx.x == 0 && tid < B) y[(size_t)tid*NT1] = fc[tid] * 0.01f;
}

// ---------------- K4: sparse GEMM1 + column-sums (atomic accumulate) --------
// 128 cols per CTA (8 x-blocks), 400 rows per CTA (50 y-blocks) = 400 CTAs,
// 3 CTAs/SM. Inner loop identical in structure to the proven R5 kernel:
// conditional w loads (skip all-zero warp-rows), scalar FMA, acc[8][4].
__global__ void __launch_bounds__(256,3) k4_sparse(const float* __restrict__ w1,
                                                   const float* __restrict__ lng,
                                                   const float* __restrict__ lnb){
    __shared__ __align__(16) float w_t[2][G4*128];    // 16 KB
    __shared__ float cnt_t[2][G4*64];                 // 8 KB
    __shared__ float gb[2][2*G4];
    int tid = threadIdx.x, lane = tid & 31, wid = tid >> 5;
    int cbase = blockIdx.x * 128;
    int jbase = blockIdx.y * RPB;

    float acc[8][4];
    #pragma unroll
    for (int i = 0; i < 8; i++)
        #pragma unroll
        for (int u = 0; u < 4; u++) acc[i][u] = 0.0f;
    float sgw[4] = {0,0,0,0}, sbw[4] = {0,0,0,0};
    float creg[4]; float greg = 0.0f, breg = 0.0f;

    // prologue: stage chunk 0
    {
        int jb = jbase;
        #pragma unroll
        for (int i = 0; i < 2; i++){
            int idx = i*256 + tid; int r = idx >> 5, g = idx & 31;
            cpa16(&w_t[0][r*128 + g*4], w1 + (size_t)(1 + jb + r)*1024 + cbase + g*4);
        }
        CP_COMMIT();
        #pragma unroll
        for (int i = 0; i < 4; i++){
            int idx = i*256 + tid; int r = idx >> 6, b = idx & 63;
            creg[i] = g_counts[(jb + r)*B + b];
        }
        if (tid < G4){ greg = lng[jb + tid]; breg = lnb[jb + tid]; }
        #pragma unroll
        for (int i = 0; i < 4; i++){
            int idx = i*256 + tid; int r = idx >> 6, b = idx & 63;
            cnt_t[0][r*64 + b] = creg[i];
        }
        if (tid < G4){ gb[0][tid] = greg; gb[0][G4 + tid] = breg; }
    }

    for (int ch = 0; ch < NCH4; ch++){
        int cur = ch & 1;
        CP_WAIT0();
        __syncthreads();
        if (ch + 1 < NCH4){
            int jb = jbase + (ch + 1)*G4;
            #pragma unroll
            for (int i = 0; i < 2; i++){
                int idx = i*256 + tid; int r = idx >> 5, g = idx & 31;
                cpa16(&w_t[cur^1][r*128 + g*4], w1 + (size_t)(1 + jb + r)*1024 + cbase + g*4);
            }
            CP_COMMIT();
            #pragma unroll
            for (int i = 0; i < 4; i++){
                int idx = i*256 + tid; int r = idx >> 6, b = idx & 63;
                creg[i] = g_counts[(jb + r)*B + b];
            }
            if (tid < G4){ greg = lng[jb + tid]; breg = lnb[jb + tid]; }
        }
        // compute on cur
        for (int r = 0; r < G4; r++){
            float gj = gb[cur][r];
            if (wid == 0){
                float bj = gb[cur][G4 + r];
                #pragma unroll
                for (int u = 0; u < 4; u++){
                    float w = w_t[cur][r*128 + lane + 32*u];
                    sgw[u] += gj * w; sbw[u] += bj * w;
                }
            }
            float cv[8]; float s = 0.0f;
            #pragma unroll
            for (int i = 0; i < 8; i++){ cv[i] = cnt_t[cur][r*64 + wid*8 + i]; s += cv[i]; }
            if (s != 0.0f){                          // warp-uniform
                float wv[4];
                #pragma unroll
                for (int u = 0; u < 4; u++) wv[u] = w_t[cur][r*128 + lane + 32*u];
                #pragma unroll
                for (int i = 0; i < 8; i++){
                    if (cv[i] != 0.0f){              // warp-uniform
                        float v = cv[i] * gj;
                        #pragma unroll
                        for (int u = 0; u < 4; u++) acc[i][u] += v * wv[u];
                    }
                }
            }
        }
        if (ch + 1 < NCH4){
            #pragma unroll
            for (int i = 0; i < 4; i++){
                int idx = i*256 + tid; int r = idx >> 6, b = idx & 63;
                cnt_t[cur^1][r*64 + b] = creg[i];
            }
            if (tid < G4){ gb[cur^1][tid] = greg; gb[cur^1][G4 + tid] = breg; }
        }
    }

    // accumulate into L2-resident global accumulators (REDG, no read-back)
    #pragma unroll
    for (int i = 0; i < 8; i++)
        #pragma unroll
        for (int u = 0; u < 4; u++)
            atomicAdd(&g_accum[(wid*8 + i)*1024 + cbase + lane + 32*u], acc[i][u]);
    if (wid == 0){
        #pragma unroll
        for (int u = 0; u < 4; u++){
            atomicAdd(&g_asgw[cbase + lane + 32*u], sgw[u]);
            atomicAdd(&g_asbw[cbase + lane + 32*u], sbw[u]);
        }
    }
}

// ---------------- K5 fused: finalize + gelu + LayerNorm -> h2 ---------------
__global__ void __launch_bounds__(256) k5_fused(const float* __restrict__ w1,
                                                const float* __restrict__ b1,
                                                const float* __restrict__ fc,
                                                const float* __restrict__ g2,
                                                const float* __restrict__ b2){
    __shared__ float r1[256], r2[256];
    int b = blockIdx.x, tid = threadIdx.x;
    float mu_b = g_mu[b], rs_b = g_rstd[b];
    float fcv = fc[b] * 0.01f;
    float h[4]; float s_sum = 0.0f, s_sq = 0.0f;
    #pragma unroll
    for (int i = 0; i < 4; i++){
        int k = i*256 + tid;
        float logit = fcv * w1[k] + g_asbw[k] - mu_b*rs_b*g_asgw[k]
                    + rs_b * g_accum[b*1024 + k] + b1[k];
        h[i] = gelu_exact(logit);
        s_sum += h[i]; s_sq += h[i]*h[i];
    }
    r1[tid] = s_sum; r2[tid] = s_sq; __syncthreads();
    for (int o = 128; o > 0; o >>= 1){
        if (tid < o){ r1[tid] += r1[tid+o]; r2[tid] += r2[tid+o]; }
        __syncthreads();
    }
    float mu = r1[0] * (1.0f/1024.0f);
    float var = r2[0] * (1.0f/1024.0f) - mu*mu;
    float rs = rsqrtf(var + 1e-5f);
    #pragma unroll
    for (int i = 0; i < 4; i++){
        int k = i*256 + tid;
        g_h2[b*1024 + k] = (h[i] - mu)*rs*g2[k] + b2[k];
    }
}

// ---------------- small GEMM: split-K partial + reduce ----------------------
template<int K, int N, int KPER>
__global__ void __launch_bounds__(256) sg_part(const float* __restrict__ A,
                                               const float* __restrict__ W,
                                               float* __restrict__ P){
    __shared__ float a_s[64*32];
    __shared__ float w_s[32*64];
    int tid = threadIdx.x, lane = tid & 31, wid = tid >> 5;
    int cbase = blockIdx.x*64, kbase = blockIdx.y*KPER;
    float acc[8][2] = {};
    for (int kc = kbase; kc < kbase + KPER; kc += 32){
        #pragma unroll
        for (int i = 0; i < 8; i++){
            int idx = i*256 + tid; int b = idx >> 5, kk = idx & 31;
            a_s[b*32 + kk] = A[b*K + kc + kk];
        }
        #pragma unroll
        for (int i = 0; i < 8; i++){
            int idx = i*256 + tid; int kk = idx >> 6, c = idx & 63;
            w_s[kk*64 + c] = W[(size_t)(kc + kk)*N + cbase + c];
        }
        __syncthreads();
        #pragma unroll
        for (int kk = 0; kk < 32; kk++){
            float av[8], wv0, wv1;
            #pragma unroll
            for (int i = 0; i < 8; i++) av[i] = a_s[(wid*8 + i)*32 + kk];
            wv0 = w_s[kk*64 + lane]; wv1 = w_s[kk*64 + lane + 32];
            #pragma unroll
            for (int i = 0; i < 8; i++){
                acc[i][0] += av[i]*wv0;
                acc[i][1] += av[i]*wv1;
            }
        }
        __syncthreads();
    }
    #pragma unroll
    for (int i = 0; i < 8; i++){
        P[blockIdx.y*(64*N) + (wid*8 + i)*N + cbase + lane]      = acc[i][0];
        P[blockIdx.y*(64*N) + (wid*8 + i)*N + cbase + lane + 32] = acc[i][1];
    }
}

template<int S, int N, bool ACT>
__global__ void sg_reduce(const float* __restrict__ P, const float* __restrict__ bias,
                          float* __restrict__ out, float* __restrict__ out2){
    int i = blockIdx.x*256 + threadIdx.x;
    if (i >= 64*N) return;
    float s = bias[i % N];
    #pragma unroll
    for (int p = 0; p < S; p++) s += P[p*64*N + i];
    if (ACT) s = gelu_exact(s);
    out[i] = s;
    if (out2) out2[i] = s;
}

// ---------------- K10: decoder GEMM [64x1024]@[1024x20001] ------------------
#define KC10 16
__global__ void __launch_bounds__(256,2) k10_part(const float* __restrict__ wd2,
                                                  float* __restrict__ P){
    extern __shared__ __align__(16) float dsm[];
    float* w_s  = dsm;          // [2][16*272]
    float* d_sm = dsm + 8704;   // [2][16*130]
    int tid = threadIdx.x, lane = tid & 31, wid = tid >> 5;
    int cbase = blockIdx.x * 272;
    int kbase = blockIdx.y * 256;

    unsigned long long acc[8][4];
    float accx[8];
    #pragma unroll
    for (int i = 0; i < 8; i++){
        accx[i] = 0.0f;
        #pragma unroll
        for (int j = 0; j < 4; j++) acc[i][j] = 0ull;
    }
    float dreg[4];

    {
        #pragma unroll
        for (int i = 0; i < 17; i++){
            int idx = i*256 + tid; int r = idx / 272, c = idx - r*272;
            int gc = cbase + c;
            float* dst = w_s + r*272 + c;
            if (gc < NT1) cpa4(dst, wd2 + (size_t)(kbase + r)*NT1 + gc);
            else *dst = 0.0f;
        }
        CP_COMMIT();
        #pragma unroll
        for (int i = 0; i < 4; i++){
            int idx = i*256 + tid; int b = idx >> 4, k = idx & 15;
            dreg[i] = g_dd[b*1024 + kbase + k];
        }
        #pragma unroll
        for (int i = 0; i < 4; i++){
            int idx = i*256 + tid; int b = idx >> 4, k = idx & 15;
            d_sm[k*130 + 2*b] = dreg[i]; d_sm[k*130 + 2*b + 1] = dreg[i];
        }
    }

    for (int ch = 0; ch < 16; ch++){
        int cur = ch & 1;
        CP_WAIT0();
        __syncthreads();
        if (ch + 1 < 16){
            int kpos = kbase + (ch + 1)*KC10;
            float* wdst = w_s + (cur^1)*4352;
            #pragma unroll
            for (int i = 0; i < 17; i++){
                int idx = i*256 + tid; int r = idx / 272, c = idx - r*272;
                int gc = cbase + c;
                float* dst = wdst + r*272 + c;
                if (gc < NT1) cpa4(dst, wd2 + (size_t)(kpos + r)*NT1 + gc);
                else *dst = 0.0f;
            }
            CP_COMMIT();
            #pragma unroll
            for (int i = 0; i < 4; i++){
                int idx = i*256 + tid; int b = idx >> 4, k = idx & 15;
                dreg[i] = g_dd[b*1024 + kpos + k];
            }
        }
        const float* wb = w_s + cur*4352;
        const float* db = d_sm + cur*2080;
        #pragma unroll 4
        for (int k = 0; k < KC10; k++){
            const float* wrow = wb + k*272;
            ulonglong2 wg0 = *(const ulonglong2*)(wrow + 4*lane);
            ulonglong2 wg1 = *(const ulonglong2*)(wrow + 128 + 4*lane);
            float wex = wrow[256 + (lane & 15)];
            const float* drow = db + k*130;
            #pragma unroll
            for (int i = 0; i < 8; i++){
                int b = wid*8 + i;
                unsigned long long dv = *(const unsigned long long*)(drow + 2*b);
                FMA2(acc[i][0], dv, wg0.x); FMA2(acc[i][1], dv, wg0.y);
                FMA2(acc[i][2], dv, wg1.x); FMA2(acc[i][3], dv, wg1.y);
                float dsc = __uint_as_float((unsigned)dv);
                accx[i] = fmaf(dsc, wex, accx[i]);
            }
        }
        if (ch + 1 < 16){
            float* ddst = d_sm + (cur^1)*2080;
            #pragma unroll
            for (int i = 0; i < 4; i++){
                int idx = i*256 + tid; int b = idx >> 4, k = idx & 15;
                ddst[k*130 + 2*b] = dreg[i]; ddst[k*130 + 2*b + 1] = dreg[i];
            }
        }
    }

    size_t obase = (size_t)blockIdx.y * (B*NTP);
    #pragma unroll
    for (int i = 0; i < 8; i++){
        float* rowp = P + obase + (size_t)(wid*8 + i)*NTP + cbase;
        float l0, h0, l1, h1;
        UNPK(l0,h0,acc[i][0]); UNPK(l1,h1,acc[i][1]);
        *(float4*)(rowp + 4*lane) = make_float4(l0, h0, l1, h1);
        UNPK(l0,h0,acc[i][2]); UNPK(l1,h1,acc[i][3]);
        *(float4*)(rowp + 128 + 4*lane) = make_float4(l0, h0, l1, h1);
        if (lane < 16) rowp[256 + lane] = accx[i];
    }
}

__global__ void k10_reduce(const float* __restrict__ P, const float* __restrict__ bd2,
                           float* __restrict__ dec){
    int i = blockIdx.x*256 + threadIdx.x;
    if (i >= B*NT1) return;
    int b = i / NT1;
    int c = i - b*NT1;
    float s = bd2[c];
    #pragma unroll
    for (int p = 0; p < 4; p++) s += P[(size_t)p*(B*NTP) + (size_t)b*NTP + c];
    dec[i] = s;
}

// ---------------- launch -----------------------------------------------------
extern "C" void kernel_launch(void* const* d_in, const int* in_sizes, int n_in,
                              void* d_out, int out_size){
    const int*   tags = (const int*)  d_in[0];
    const float* fc   = (const float*)d_in[1];
    const float* lng  = (const float*)d_in[2];
    const float* lnb  = (const float*)d_in[3];
    const float* w1   = (const float*)d_in[4];
    const float* b1   = (const float*)d_in[5];
    const float* ln2g = (const float*)d_in[6];
    const float* ln2b = (const float*)d_in[7];
    const float* we1  = (const float*)d_in[8];
    const float* be1  = (const float*)d_in[9];
    const float* we2  = (const float*)d_in[10];
    const float* be2  = (const float*)d_in[11];
    const float* wd1  = (const float*)d_in[12];
    const float* bd1  = (const float*)d_in[13];
    const float* wd2  = (const float*)d_in[14];
    const float* bd2  = (const float*)d_in[15];
    float* out = (float*)d_out;

    float *p_counts, *p_h2, *p_h3, *p_enc, *p_dd, *p_pbuf, *p_pacc;
    cudaGetSymbolAddress((void**)&p_counts, g_counts);
    cudaGetSymbolAddress((void**)&p_h2,     g_h2);
    cudaGetSymbolAddress((void**)&p_h3,     g_h3);
    cudaGetSymbolAddress((void**)&p_enc,    g_encb);
    cudaGetSymbolAddress((void**)&p_dd,     g_dd);
    cudaGetSymbolAddress((void**)&p_pbuf,   g_pbuf);
    cudaGetSymbolAddress((void**)&p_pacc,   g_pacc);

    static int smem_set = 0;
    if (!smem_set){
        cudaFuncSetAttribute(k10_part, cudaFuncAttributeMaxDynamicSharedMemorySize, 51456);
        smem_set = 1;
    }

    cudaMemsetAsync(p_counts, 0, (size_t)NT*B*sizeof(float));
    k1_scatter<<<32, 256>>>(tags);
    k2a_stats<<<160, 256>>>();
    k3_y<<<313, 256>>>(fc, lng, lnb, out);
    k4_sparse<<<dim3(8, RC), 256>>>(w1, lng, lnb);
    k5_fused<<<64, 256>>>(w1, b1, fc, ln2g, ln2b);

    // h2 @ we1 (1024->1024) + gelu
    sg_part<1024, 1024, 32><<<dim3(16, 32), 256>>>(p_h2, we1, p_pbuf);
    sg_reduce<32, 1024, true><<<256, 256>>>(p_pbuf, be1, p_h3, (float*)0);
    // h3 @ we2 (1024->256) -> enc (output #2)
    sg_part<1024, 256, 32><<<dim3(4, 32), 256>>>(p_h3, we2, p_pbuf);
    sg_reduce<32, 256, false><<<64, 256>>>(p_pbuf, be2, out + ENC_OFF, p_enc);
    // enc @ wd1 (256->1024) + gelu
    sg_part<256, 1024, 32><<<dim3(16, 8), 256>>>(p_enc, wd1, p_pbuf);
    sg_reduce<8, 1024, true><<<256, 256>>>(p_pbuf, bd1, p_dd, (float*)0);

    // dd @ wd2 (1024->20001) -> dec (output #3)
    k10_part<<<dim3(74, 4), 256, 51456>>>(wd2, p_pacc);
    k10_reduce<<<5001, 256>>>(p_pacc, bd2, out + DEC_OFF);
}